// round 5
// baseline (speedup 1.0000x reference)
#include <cuda_runtime.h>
#include <cuda_bf16.h>
#include <cstdint>

// ---------------------------------------------------------------------------
// QuantumLayer: out[b,m] = e^{i*kappa*m^2} * sum_n G[m,n] * state[b,n]
// GEMM form: out[B,64] = X[B,64] @ W[64,64], X=[re|im],
//   cols 2m/2m+1 = Re/Im (with Kerr folded into W).
// bf16 mma.m16n8k16, hi/lo split: D = Xh*Wh + Xl*Wh + Xh*Wl.
//
// Round 5: PDL overlap of build_G with apply_k's load phase; boundless fast
// path (B % 256 == 0); loads -> griddep sync -> W smem fill ordering.
// ---------------------------------------------------------------------------

#define TPB 256

// [js][ 4*kt + t ] uint4, row stride 17 (16 + 1 pad).
__device__ uint4 g_Wf[64 * 17];

// ======================== build W (1 warp, fp64) ===========================
struct dc { double re, im; };
__device__ __forceinline__ dc dmul(dc a, dc b){ return {a.re*b.re - a.im*b.im, a.re*b.im + a.im*b.re}; }
__device__ __forceinline__ dc dadd(dc a, dc b){ return {a.re + b.re, a.im + b.im}; }
__device__ __forceinline__ dc dscale(dc a, double s){ return {a.re*s, a.im*s}; }

__global__ void build_G(const float* __restrict__ gre, const float* __restrict__ gim,
                        const float* __restrict__ phip, const float* __restrict__ zre,
                        const float* __restrict__ zim, const float* __restrict__ kapp)
{
    // Let the dependent kernel start its (independent) state loads now.
    cudaTriggerProgrammaticLaunchCompletion();

    const int m = threadIdx.x;  // 0..31, lane == Fock row index
    const double gr  = gre[0],  gi  = gim[0];
    const double phi = phip[0];
    const double zr  = zre[0],  zi  = zim[0];
    const double kap = kapp[0];

    const double sq_m  = sqrt((double)m);
    const double rsq_m = (m > 0) ? 1.0 / sq_m : 0.0;
    auto SQ  = [&](int k){ return __shfl_sync(0xffffffffu, sq_m,  k); };
    auto RSQ = [&](int k){ return __shfl_sync(0xffffffffu, rsq_m, k); };

    const double r2 = zr*zr + zi*zi;
    const double r  = sqrt(r2);
    dc eid;                                   // e^{i delta} = zeta/|zeta|
    if (r > 0.0) { eid = { zr / r, zi / r }; } else { eid = { 1.0, 0.0 }; }

    const double er  = exp(r);
    const double ei  = 1.0 / er;
    const double ch  = 0.5 * (er + ei);
    const double T   = (0.5 * (er - ei)) / ch; // tanh r
    const double sech= 1.0 / ch;

    double sph, cph; sincos(phi, &sph, &cph);
    const dc eiphi  = { cph, sph };
    const dc e2iphi = dmul(eiphi, eiphi);
    const dc eidp   = dmul(eid, e2iphi);      // e^{i(delta + 2 phi)}

    const dc gamma = { gr,  gi };
    const dc gbar  = { gr, -gi };

    const dc gb2 = dmul(gbar, gbar);
    const dc t1  = dscale(dmul(gb2, eidp), T);
    const double zr_ = -0.5*(gr*gr + gi*gi + t1.re);
    const double zi_ = -0.5*t1.im;
    double s0, c0p; sincos(zi_, &s0, &c0p);
    const double ez  = exp(zr_) * sqrt(sech);
    const dc g00 = { ez * c0p, ez * s0 };

    const dc A = dadd(gamma, dscale(dmul(gbar, eidp), T));
    const dc B = dscale(eidp, T);
    const dc P = dscale(eiphi, sech);
    const dc Q = { eid.re * T, -eid.im * T };  // e^{-i delta} tanh r

    // --- column 0: serial recurrence (replicated per lane, lane keeps row m)
    dc c0 = g00;
    {
        dc gm1 = g00, gm2 = {0.0, 0.0};
        for (int k = 1; k < 32; k++) {
            dc ag = dmul(A, gm1);
            dc bg = dscale(dmul(B, gm2), SQ(k - 1));
            dc g  = dscale({ag.re - bg.re, ag.im - bg.im}, RSQ(k));
            if (m == k) c0 = g;
            gm2 = gm1; gm1 = g;
        }
    }

    double sk, ck; sincos(kap * (double)(m * m), &sk, &ck);
    const dc kerr = { ck, sk };

    // Write W^T[j_gmem][k] into the permuted fragment-native layout.
    auto put = [&](int j_gmem, int k, float x){
        __nv_bfloat16 h = __float2bfloat16(x);
        float l = x - __bfloat162float(h);
        // N-permutation: gmem col -> (nt, pos) -> storage row js
        int u  = j_gmem >> 4, rem = j_gmem & 15;
        int tt = rem >> 2,    w4  = rem & 3;
        int nt = 2*u + (w4 >> 1);
        int p  = 2*tt + (w4 & 1);
        int js = nt*8 + p;
        // K location: chunk c, thread t, quad q
        int c = k >> 4, t = (k >> 2) & 3, q = k & 3;
        __nv_bfloat16* base = reinterpret_cast<__nv_bfloat16*>(&g_Wf[js*17 + c*4 + t]);
        base[q]     = h;                       // words x,y = b0h,b1h
        base[4 + q] = __float2bfloat16(l);     // words z,w = b0l,b1l
    };
    auto write_col = [&](int n, dc v){
        dc w = dmul(kerr, v);
        float wr = (float)w.re, wi = (float)w.im;
        put(2*m,     n,      wr);
        put(2*m + 1, n,      wi);
        put(2*m,     32 + n, -wi);
        put(2*m + 1, 32 + n, wr);
    };

    dc cur = c0, prev = {0.0, 0.0};
    write_col(0, cur);

    for (int n = 0; n < 31; n++) {
        double ur = __shfl_up_sync(0xffffffffu, cur.re, 1);
        double ui = __shfl_up_sync(0xffffffffu, cur.im, 1);
        if (m == 0) { ur = 0.0; ui = 0.0; }
        dc gc = dmul(gbar, cur);
        dc term = { sq_m * ur - gc.re, sq_m * ui - gc.im };
        dc pt = dmul(P, term);
        dc qp = dscale(dmul(Q, prev), SQ(n));
        dc next = dscale({pt.re + qp.re, pt.im + qp.im}, RSQ(n + 1));
        prev = cur; cur = next;
        write_col(n + 1, cur);
    }
}

// ============================ apply (tensor) ===============================

__device__ __forceinline__ void split2(float x, float y, uint32_t& h, uint32_t& l)
{
    uint32_t hh;
    asm("cvt.rn.bf16x2.f32 %0, %1, %2;" : "=r"(hh) : "f"(y), "f"(x)); // lo=x, hi=y
    float hx = __uint_as_float(hh << 16);
    float hy = __uint_as_float(hh & 0xffff0000u);
    float lx = x - hx;
    float ly = y - hy;
    uint32_t ll;
    asm("cvt.rn.bf16x2.f32 %0, %1, %2;" : "=r"(ll) : "f"(ly), "f"(lx));
    h = hh; l = ll;
}

__device__ __forceinline__ void mma_bf16(float* c,
                                         uint32_t a0, uint32_t a1, uint32_t a2, uint32_t a3,
                                         uint32_t b0, uint32_t b1)
{
    asm("mma.sync.aligned.m16n8k16.row.col.f32.bf16.bf16.f32 "
        "{%0,%1,%2,%3}, {%4,%5,%6,%7}, {%8,%9}, {%0,%1,%2,%3};"
        : "+f"(c[0]), "+f"(c[1]), "+f"(c[2]), "+f"(c[3])
        : "r"(a0), "r"(a1), "r"(a2), "r"(a3), "r"(b0), "r"(b1));
}

template <bool FULL>
__device__ __forceinline__ void apply_body(
    const float* __restrict__ sre, const float* __restrict__ sim,
    float* __restrict__ out, int B, uint4* sW)
{
    const int warp = threadIdx.x >> 5;
    const int lane = threadIdx.x & 31;
    const int g    = lane >> 2;     // 0..7
    const int t    = lane & 3;      // 0..3

    const int wbase = blockIdx.x * 256 + warp * 32;   // 32 states per warp

    int row0[2], row1[2];
#pragma unroll
    for (int tile = 0; tile < 2; tile++) {
        row0[tile] = wbase + tile * 16 + g;
        row1[tile] = row0[tile] + 8;
    }

    // ---- front-batched A loads: 16x LDG.128 (issued BEFORE grid-dep sync)
    float4 L[16];
#pragma unroll
    for (int tile = 0; tile < 2; tile++) {
        int rc0 = row0[tile], rc1 = row1[tile];
        if (!FULL) { rc0 = (rc0 < B) ? rc0 : (B - 1); rc1 = (rc1 < B) ? rc1 : (B - 1); }
        const float4* pr0 = reinterpret_cast<const float4*>(sre + (size_t)rc0 * 32);
        const float4* pi0 = reinterpret_cast<const float4*>(sim + (size_t)rc0 * 32);
        const float4* pr1 = reinterpret_cast<const float4*>(sre + (size_t)rc1 * 32);
        const float4* pi1 = reinterpret_cast<const float4*>(sim + (size_t)rc1 * 32);
        L[tile * 8 + 0] = pr0[t];
        L[tile * 8 + 1] = pr0[t + 4];
        L[tile * 8 + 2] = pi0[t];
        L[tile * 8 + 3] = pi0[t + 4];
        L[tile * 8 + 4] = pr1[t];
        L[tile * 8 + 5] = pr1[t + 4];
        L[tile * 8 + 6] = pi1[t];
        L[tile * 8 + 7] = pi1[t + 4];
    }

    // Wait for build_G (PDL edge), then pull W into shared.
    cudaGridDependencySynchronize();
    for (int i = threadIdx.x; i < 64 * 17; i += TPB) sW[i] = g_Wf[i];
    __syncthreads();

    // A fragments
    uint32_t Ah[2][4][4], Al[2][4][4];
#pragma unroll
    for (int tile = 0; tile < 2; tile++) {
#pragma unroll
        for (int kt = 0; kt < 4; kt++) {
            float4 v0 = L[tile * 8 + kt];
            float4 v1 = L[tile * 8 + 4 + kt];
            split2(v0.x, v0.y, Ah[tile][kt][0], Al[tile][kt][0]);
            split2(v0.z, v0.w, Ah[tile][kt][2], Al[tile][kt][2]);
            split2(v1.x, v1.y, Ah[tile][kt][1], Al[tile][kt][1]);
            split2(v1.z, v1.w, Ah[tile][kt][3], Al[tile][kt][3]);
        }
    }

#pragma unroll
    for (int u = 0; u < 4; u++) {
        float acc[2][2][4];                 // [ntHalf][tile][frag]
#pragma unroll
        for (int a = 0; a < 2; a++)
#pragma unroll
            for (int b = 0; b < 2; b++)
#pragma unroll
                for (int c = 0; c < 4; c++) acc[a][b][c] = 0.f;

#pragma unroll
        for (int h2 = 0; h2 < 2; h2++) {
            const int nt = 2 * u + h2;
            const uint4* bp = &sW[(nt * 8 + g) * 17 + t];
#pragma unroll
            for (int kt = 0; kt < 4; kt++) {
                uint4 b = bp[kt * 4];       // {b0h, b1h, b0l, b1l}
#pragma unroll
                for (int tile = 0; tile < 2; tile++) {
                    mma_bf16(acc[h2][tile], Ah[tile][kt][0], Ah[tile][kt][1],
                                            Ah[tile][kt][2], Ah[tile][kt][3], b.x, b.y);
                    mma_bf16(acc[h2][tile], Al[tile][kt][0], Al[tile][kt][1],
                                            Al[tile][kt][2], Al[tile][kt][3], b.x, b.y);
                    mma_bf16(acc[h2][tile], Ah[tile][kt][0], Ah[tile][kt][1],
                                            Ah[tile][kt][2], Ah[tile][kt][3], b.z, b.w);
                }
            }
        }

        // stores: gmem cols 16u + 4t .. +3 (STG.128)
        const int colb = 16 * u + 4 * t;
#pragma unroll
        for (int tile = 0; tile < 2; tile++) {
            if (FULL || row0[tile] < B) {
                float4 v = make_float4(acc[0][tile][0], acc[0][tile][1],
                                       acc[1][tile][0], acc[1][tile][1]);
                *reinterpret_cast<float4*>(out + (size_t)row0[tile] * 64 + colb) = v;
            }
            if (FULL || row1[tile] < B) {
                float4 v = make_float4(acc[0][tile][2], acc[0][tile][3],
                                       acc[1][tile][2], acc[1][tile][3]);
                *reinterpret_cast<float4*>(out + (size_t)row1[tile] * 64 + colb) = v;
            }
        }
    }
}

__global__ void __launch_bounds__(TPB, 2)
apply_k(const float* __restrict__ sre, const float* __restrict__ sim,
        float* __restrict__ out, int B)
{
    __shared__ uint4 sW[64 * 17];
    if ((blockIdx.x + 1) * 256 <= B) {
        apply_body<true>(sre, sim, out, B, sW);
    } else {
        apply_body<false>(sre, sim, out, B, sW);
    }
}

extern "C" void kernel_launch(void* const* d_in, const int* in_sizes, int n_in,
                              void* d_out, int out_size)
{
    const float* state_re = (const float*)d_in[0];
    const float* state_im = (const float*)d_in[1];
    const float* gamma_re = (const float*)d_in[2];
    const float* gamma_im = (const float*)d_in[3];
    const float* phi      = (const float*)d_in[4];
    const float* zeta_re  = (const float*)d_in[5];
    const float* zeta_im  = (const float*)d_in[6];
    const float* kappa    = (const float*)d_in[7];

    const int B = in_sizes[0] / 32;

    build_G<<<1, 32>>>(gamma_re, gamma_im, phi, zeta_re, zeta_im, kappa);

    const int blocks = (B + 255) / 256;   // 256 states per CTA (8 warps x 32)

    // Launch apply_k with programmatic stream serialization (PDL): it starts
    // while build_G runs; apply_k grid-dep-syncs before reading g_Wf.
    cudaLaunchConfig_t cfg = {};
    cfg.gridDim  = dim3(blocks, 1, 1);
    cfg.blockDim = dim3(TPB, 1, 1);
    cfg.dynamicSmemBytes = 0;
    cfg.stream = 0;
    cudaLaunchAttribute attr[1];
    attr[0].id = cudaLaunchAttributeProgrammaticStreamSerialization;
    attr[0].val.programmaticStreamSerializationAllowed = 1;
    cfg.attrs = attr;
    cfg.numAttrs = 1;

    cudaError_t e = cudaLaunchKernelEx(&cfg, apply_k, state_re, state_im,
                                       (float*)d_out, B);
    if (e != cudaSuccess) {
        // Fallback: plain launch (grid-dep sync is then a no-op).
        apply_k<<<blocks, TPB>>>(state_re, state_im, (float*)d_out, B);
    }
}